// round 1
// baseline (speedup 1.0000x reference)
#include <cuda_runtime.h>
#include <math.h>

#define N_NODES 160000
#define N_EDGES 640000
#define N_GRAPHS 8000
#define NPG 20            // nodes per graph (160000/8000)
#define F0 74
#define H 63
#define MAXD 10
#define PH 128
#define PD 256
#define BN_EPS 1e-5f
#define NB1 157           // ceil(160000/1024)

// ---------------- device scratch (static allocation; no runtime mallocs) -----
__device__ int   g_deg[N_NODES];
__device__ int   g_off[N_NODES + 1];
__device__ int   g_cur[N_NODES];
__device__ int   g_csr[N_EDGES];
__device__ int   g_didx[N_NODES];
__device__ int   g_aux[NB1];
__device__ float g_zA[N_NODES * H];
__device__ float g_zB[N_NODES * H];
__device__ float g_hn[(size_t)N_NODES * PH];
__device__ float g_sum[H];
__device__ float g_sq[H];
__device__ float g_scale[H];
__device__ float g_shift[H];

// ---------------- init: zero degree + stat accumulators ----------------------
__global__ void k_init() {
    int i = blockIdx.x * blockDim.x + threadIdx.x;
    if (i < N_NODES) g_deg[i] = 0;
    if (i < H) { g_sum[i] = 0.f; g_sq[i] = 0.f; }
}

// ---------------- degree count ----------------------------------------------
__global__ void k_count(const int* __restrict__ dst) {
    int e = blockIdx.x * blockDim.x + threadIdx.x;
    if (e < N_EDGES) atomicAdd(&g_deg[dst[e]], 1);
}

// ---------------- exclusive scan of g_deg -> g_off (3 kernels) ---------------
__global__ void k_scan1() {
    __shared__ int s[256];
    int t = threadIdx.x;
    int base = blockIdx.x * 1024;
    int v[4]; int mysum = 0;
#pragma unroll
    for (int k = 0; k < 4; k++) {
        int idx = base + t * 4 + k;
        v[k] = (idx < N_NODES) ? g_deg[idx] : 0;
        mysum += v[k];
    }
    s[t] = mysum;
    __syncthreads();
    for (int off = 1; off < 256; off <<= 1) {
        int x = (t >= off) ? s[t - off] : 0;
        __syncthreads();
        s[t] += x;
        __syncthreads();
    }
    int run = s[t] - mysum;  // exclusive prefix within block
#pragma unroll
    for (int k = 0; k < 4; k++) {
        int idx = base + t * 4 + k;
        if (idx < N_NODES) g_off[idx] = run;
        run += v[k];
    }
    if (t == 255) g_aux[blockIdx.x] = s[255];
}

__global__ void k_scan2() {
    // single thread, 157 iterations — negligible
    int carry = 0;
    for (int b = 0; b < NB1; b++) { int x = g_aux[b]; g_aux[b] = carry; carry += x; }
}

__global__ void k_scan3() {
    int i = blockIdx.x * blockDim.x + threadIdx.x;
    if (i < N_NODES) {
        int o = g_off[i] + g_aux[i >> 10];
        g_off[i] = o;
        g_cur[i] = o;
        int d = g_deg[i];
        d = (d < 1) ? 1 : (d > MAXD ? MAXD : d);
        g_didx[i] = d - 1;
    }
    if (i == 0) g_off[N_NODES] = N_EDGES;
}

// ---------------- CSR scatter ------------------------------------------------
__global__ void k_scatter(const int* __restrict__ src, const int* __restrict__ dst) {
    int e = blockIdx.x * blockDim.x + threadIdx.x;
    if (e < N_EDGES) {
        int p = atomicAdd(&g_cur[dst[e]], 1);
        g_csr[p] = src[e];
    }
}

// ---------------- fused NF layer ----------------------------------------------
// MODE 0: in = feats (param, no affine), out = g_zB
// MODE 1: in = g_zB (apply affine),     out = g_zA
// MODE 2: in = g_zA (apply affine),     out = g_zB
template <int FIN, int MODE>
__global__ void __launch_bounds__(256)
k_layer(const float* __restrict__ ext_in, const float* __restrict__ W,
        const float* __restrict__ b) {
    const float* in   = (MODE == 0) ? ext_in : (MODE == 1 ? g_zB : g_zA);
    float*       zout = (MODE == 1) ? g_zA : g_zB;

    __shared__ float stot[8][FIN];
    __shared__ float ssum[H], ssq[H];

    int t = threadIdx.x, w = t >> 5, lane = t & 31;
    if (t < H) { ssum[t] = 0.f; ssq[t] = 0.f; }

    int n = blockIdx.x * 8 + w;  // grid is exactly N/8 blocks
    int s0 = g_off[n], s1 = g_off[n + 1];

    // ---- phase 1: gather (self + neighbor sum), raw; affine folded in after
    constexpr int KK = (FIN + 31) / 32;
    float acc[KK];
#pragma unroll
    for (int k = 0; k < KK; k++) {
        int f = lane + 32 * k;
        acc[k] = (f < FIN) ? in[n * FIN + f] : 0.f;
    }
    for (int j = s0; j < s1; j++) {
        int sc = g_csr[j];
        const float* row = in + (size_t)sc * FIN;
#pragma unroll
        for (int k = 0; k < KK; k++) {
            int f = lane + 32 * k;
            if (f < FIN) acc[k] += row[f];
        }
    }
    float cnt = (float)(1 + s1 - s0);
#pragma unroll
    for (int k = 0; k < KK; k++) {
        int f = lane + 32 * k;
        if (f < FIN) {
            float v = acc[k];
            if (MODE != 0) v = v * g_scale[f] + cnt * g_shift[f];
            stot[w][f] = v;
        }
    }
    __syncthreads();

    // ---- phase 2: degree-bucketed linear + relu
    int d = g_didx[n];
    const float* Wd = W + d * FIN * H;
    float z0 = b[d * H + lane];                               // o = lane  (0..31)
    float z1 = (lane < H - 32) ? b[d * H + 32 + lane] : 0.f;  // o = 32+lane (32..62)
    for (int i = 0; i < FIN; i++) {
        float tt = stot[w][i];
        z0 = fmaf(tt, Wd[i * H + lane], z0);
        if (lane < H - 32) z1 = fmaf(tt, Wd[i * H + 32 + lane], z1);
    }
    z0 = fmaxf(z0, 0.f);
    z1 = fmaxf(z1, 0.f);
    zout[n * H + lane] = z0;
    if (lane < H - 32) zout[n * H + 32 + lane] = z1;

    // ---- block-reduced BN statistics
    atomicAdd(&ssum[lane], z0);
    atomicAdd(&ssq[lane], z0 * z0);
    if (lane < H - 32) {
        atomicAdd(&ssum[32 + lane], z1);
        atomicAdd(&ssq[32 + lane], z1 * z1);
    }
    __syncthreads();
    if (t < H) {
        atomicAdd(&g_sum[t], ssum[t]);
        atomicAdd(&g_sq[t], ssq[t]);
    }
}

// ---------------- fold BN stats into affine (scale, shift); reset accumulators
__global__ void k_stats(const float* __restrict__ gamma, const float* __restrict__ beta) {
    int t = threadIdx.x;
    if (t >= H) return;
    float mu  = g_sum[t] * (1.f / N_NODES);
    float var = g_sq[t] * (1.f / N_NODES) - mu * mu;
    float sc  = gamma[t] * rsqrtf(var + BN_EPS);
    g_scale[t] = sc;
    g_shift[t] = beta[t] - mu * sc;
    g_sum[t] = 0.f;
    g_sq[t]  = 0.f;
}

// ---------------- node_to_graph linear: hn = affine(zB) @ W_ng + b_ng --------
#define NGNODES 8
__global__ void __launch_bounds__(128)
k_ng(const float* __restrict__ Wng, const float* __restrict__ bng) {
    __shared__ float sh[NGNODES][H];
    int t = threadIdx.x;          // 128 = output index
    int nb = blockIdx.x * NGNODES;

    for (int k = t; k < NGNODES * H; k += 128) {
        int nn = k / H, f = k - nn * H;
        sh[nn][f] = g_zB[(nb + nn) * H + f] * g_scale[f] + g_shift[f];
    }
    __syncthreads();

    float z[NGNODES];
    float bb = bng[t];
#pragma unroll
    for (int k = 0; k < NGNODES; k++) z[k] = bb;
    for (int i = 0; i < H; i++) {
        float wv = Wng[i * PH + t];
#pragma unroll
        for (int k = 0; k < NGNODES; k++) z[k] = fmaf(sh[k][i], wv, z[k]);
    }
#pragma unroll
    for (int k = 0; k < NGNODES; k++) g_hn[(size_t)(nb + k) * PH + t] = z[k];
}

// ---------------- fused readout (sum+max over 20 contiguous rows) + tanh + GEMM
#define GPB 8
__global__ void __launch_bounds__(256)
k_out(const float* __restrict__ Wtr, const float* __restrict__ btr,
      float* __restrict__ out) {
    __shared__ float sg[GPB][2 * PH];
    int t = threadIdx.x;          // 256
    int g0 = blockIdx.x * GPB;

    for (int k = t; k < GPB * PH; k += 256) {
        int gl = k >> 7, f = k & 127;
        const float* base = g_hn + (size_t)(g0 + gl) * NPG * PH + f;
        float s = 0.f, m = -3.402823466e38f;
#pragma unroll
        for (int r = 0; r < NPG; r++) {
            float v = base[(size_t)r * PH];
            s += v;
            m = fmaxf(m, v);
        }
        sg[gl][f]      = tanhf(s);
        sg[gl][PH + f] = tanhf(m);
    }
    __syncthreads();

    float z[GPB];
    float bb = btr[t];
#pragma unroll
    for (int k = 0; k < GPB; k++) z[k] = bb;
    for (int i = 0; i < 2 * PH; i++) {
        float wv = Wtr[i * PD + t];
#pragma unroll
        for (int k = 0; k < GPB; k++) z[k] = fmaf(sg[k][i], wv, z[k]);
    }
#pragma unroll
    for (int k = 0; k < GPB; k++) out[(size_t)(g0 + k) * PD + t] = z[k];
}

// ---------------- launch -------------------------------------------------------
extern "C" void kernel_launch(void* const* d_in, const int* in_sizes, int n_in,
                              void* d_out, int out_size) {
    const float* feats = (const float*)d_in[0];
    const int*   src   = (const int*)d_in[1];
    const int*   dst   = (const int*)d_in[2];
    // d_in[3] = graph_ids (contiguous 20-per-graph by construction; unused)
    const float* W0 = (const float*)d_in[4];
    const float* b0 = (const float*)d_in[5];
    const float* g0 = (const float*)d_in[6];
    const float* be0 = (const float*)d_in[7];
    const float* W1 = (const float*)d_in[8];
    const float* b1 = (const float*)d_in[9];
    const float* g1 = (const float*)d_in[10];
    const float* be1 = (const float*)d_in[11];
    const float* W2 = (const float*)d_in[12];
    const float* b2 = (const float*)d_in[13];
    const float* g2 = (const float*)d_in[14];
    const float* be2 = (const float*)d_in[15];
    const float* Wng = (const float*)d_in[16];
    const float* bng = (const float*)d_in[17];
    const float* Wtr = (const float*)d_in[18];
    const float* btr = (const float*)d_in[19];
    float* out = (float*)d_out;

    // graph build
    k_init<<<(N_NODES + 255) / 256, 256>>>();
    k_count<<<(N_EDGES + 255) / 256, 256>>>(dst);
    k_scan1<<<NB1, 256>>>();
    k_scan2<<<1, 1>>>();
    k_scan3<<<(N_NODES + 255) / 256, 256>>>();
    k_scatter<<<(N_EDGES + 255) / 256, 256>>>(src, dst);

    // 3 NF layers (gather + degree-bucketed linear + relu + BN stats)
    k_layer<F0, 0><<<N_NODES / 8, 256>>>(feats, W0, b0);
    k_stats<<<1, 64>>>(g0, be0);
    k_layer<H, 1><<<N_NODES / 8, 256>>>(nullptr, W1, b1);
    k_stats<<<1, 64>>>(g1, be1);
    k_layer<H, 2><<<N_NODES / 8, 256>>>(nullptr, W2, b2);
    k_stats<<<1, 64>>>(g2, be2);

    // node->graph projection, then fused readout + tanh + final GEMM
    k_ng<<<N_NODES / NGNODES, 128>>>(Wng, bng);
    k_out<<<N_GRAPHS / GPB, 256>>>(Wtr, btr, out);
}

// round 2
// speedup vs baseline: 1.6340x; 1.6340x over previous
#include <cuda_runtime.h>
#include <math.h>

#define N_NODES 160000
#define N_EDGES 640000
#define N_GRAPHS 8000
#define NPG 20
#define F0 74
#define H 63
#define MAXD 10
#define PH 128
#define PD 256
#define BN_EPS 1e-5f
#define NB1 157
#define TILE 64
#define NTILES 2510              // 160000/64 + 10 pad tiles
#define PERM_SZ (NTILES * TILE)

// ---------------- device scratch ---------------------------------------------
__device__ int   g_deg[N_NODES];
__device__ int   g_off[N_NODES + 1];
__device__ int   g_cur[N_NODES];
__device__ int   g_csr[N_EDGES];
__device__ int   g_didx[N_NODES];
__device__ int   g_aux[NB1];
__device__ int   g_bcnt[MAXD];
__device__ int   g_bstart[MAXD];
__device__ int   g_bfill[MAXD];
__device__ int   g_perm[PERM_SZ];
__device__ float g_zA[N_NODES * H];
__device__ float g_zB[N_NODES * H];
__device__ float g_hn[(size_t)N_NODES * PH];
__device__ float g_sum[H];
__device__ float g_sq[H];
__device__ float g_scale[H];
__device__ float g_shift[H];

// ---------------- packed f32x2 helpers (sm_103a FFMA2 path) -------------------
typedef unsigned long long u64;
__device__ __forceinline__ u64 fma2(u64 a, u64 b, u64 c) {
    u64 d;
    asm("fma.rn.f32x2 %0, %1, %2, %3;" : "=l"(d) : "l"(a), "l"(b), "l"(c));
    return d;
}
__device__ __forceinline__ u64 pack2(float lo, float hi) {
    u64 d;
    asm("mov.b64 %0, {%1, %2};" : "=l"(d) : "f"(lo), "f"(hi));
    return d;
}
__device__ __forceinline__ void unpack2(u64 v, float& lo, float& hi) {
    asm("mov.b64 {%0, %1}, %2;" : "=f"(lo), "=f"(hi) : "l"(v));
}

// ---------------- init ---------------------------------------------------------
__global__ void k_init() {
    int i = blockIdx.x * blockDim.x + threadIdx.x;
    if (i < PERM_SZ) g_perm[i] = -1;
    if (i < N_NODES) g_deg[i] = 0;
    if (i < H) { g_sum[i] = 0.f; g_sq[i] = 0.f; }
    if (i < MAXD) g_bcnt[i] = 0;
}

// ---------------- degree count -------------------------------------------------
__global__ void k_count(const int* __restrict__ dst) {
    int e = blockIdx.x * blockDim.x + threadIdx.x;
    if (e < N_EDGES) atomicAdd(&g_deg[dst[e]], 1);
}

// ---------------- scan (3 stages) ------------------------------------------------
__global__ void k_scan1() {
    __shared__ int s[256];
    int t = threadIdx.x;
    int base = blockIdx.x * 1024;
    int v[4]; int mysum = 0;
#pragma unroll
    for (int k = 0; k < 4; k++) {
        int idx = base + t * 4 + k;
        v[k] = (idx < N_NODES) ? g_deg[idx] : 0;
        mysum += v[k];
    }
    s[t] = mysum;
    __syncthreads();
    for (int off = 1; off < 256; off <<= 1) {
        int x = (t >= off) ? s[t - off] : 0;
        __syncthreads();
        s[t] += x;
        __syncthreads();
    }
    int run = s[t] - mysum;
#pragma unroll
    for (int k = 0; k < 4; k++) {
        int idx = base + t * 4 + k;
        if (idx < N_NODES) g_off[idx] = run;
        run += v[k];
    }
    if (t == 255) g_aux[blockIdx.x] = s[255];
}

__global__ void k_scan2() {  // parallel block-sum scan (was single-thread, 16 us)
    __shared__ int s[256];
    int t = threadIdx.x;
    int v = (t < NB1) ? g_aux[t] : 0;
    s[t] = v;
    __syncthreads();
    for (int off = 1; off < 256; off <<= 1) {
        int x = (t >= off) ? s[t - off] : 0;
        __syncthreads();
        s[t] += x;
        __syncthreads();
    }
    if (t < NB1) g_aux[t] = s[t] - v;  // exclusive
}

__global__ void k_scan3() {
    __shared__ int c[MAXD];
    int t = threadIdx.x;
    if (t < MAXD) c[t] = 0;
    __syncthreads();
    int i = blockIdx.x * blockDim.x + t;
    if (i < N_NODES) {
        int o = g_off[i] + g_aux[i >> 10];
        g_off[i] = o;
        g_cur[i] = o;
        int d = g_deg[i];
        d = (d < 1) ? 1 : (d > MAXD ? MAXD : d);
        g_didx[i] = d - 1;
        atomicAdd(&c[d - 1], 1);
    }
    if (i == 0) g_off[N_NODES] = N_EDGES;
    __syncthreads();
    if (t < MAXD && c[t] > 0) atomicAdd(&g_bcnt[t], c[t]);
}

// ---------------- bucket offsets (padded to TILE) -------------------------------
__global__ void k_boff() {
    if (threadIdx.x == 0) {
        int s = 0;
        for (int d = 0; d < MAXD; d++) {
            g_bstart[d] = s;
            g_bfill[d] = s;
            s += (g_bcnt[d] + TILE - 1) / TILE * TILE;
        }
    }
}

// ---------------- fill permutation (block-aggregated) ---------------------------
__global__ void k_fill() {
    __shared__ int c[MAXD], base[MAXD];
    int t = threadIdx.x;
    if (t < MAXD) c[t] = 0;
    __syncthreads();
    int i = blockIdx.x * blockDim.x + t;
    int d = 0, r = 0;
    bool valid = (i < N_NODES);
    if (valid) {
        d = g_didx[i];
        r = atomicAdd(&c[d], 1);
    }
    __syncthreads();
    if (t < MAXD && c[t] > 0) base[t] = atomicAdd(&g_bfill[t], c[t]);
    __syncthreads();
    if (valid) g_perm[base[d] + r] = i;
}

// ---------------- CSR scatter ----------------------------------------------------
__global__ void k_scatter(const int* __restrict__ src, const int* __restrict__ dst) {
    int e = blockIdx.x * blockDim.x + threadIdx.x;
    if (e < N_EDGES) {
        int p = atomicAdd(&g_cur[dst[e]], 1);
        g_csr[p] = src[e];
    }
}

// ---------------- fused NF layer: bucket-batched, W in smem, FFMA2 GEMM ----------
// MODE 0: in = feats (no affine), out = g_zB
// MODE 1: in = g_zB (affine),     out = g_zA
// MODE 2: in = g_zA (affine),     out = g_zB
template <int FIN, int MODE>
__global__ void __launch_bounds__(256)
k_layer(const float* __restrict__ ext_in, const float* __restrict__ W,
        const float* __restrict__ b) {
    const float* in   = (MODE == 0) ? ext_in : (MODE == 1 ? g_zB : g_zA);
    float*       zout = (MODE == 1) ? g_zA : g_zB;

    constexpr int SP = 66;  // stot row pitch: even (pair-aligned) + low conflict
    __shared__ float sW[FIN * 64];
    __shared__ float sT[FIN * SP];
    __shared__ float sb[64];
    __shared__ float ssum[H], ssq[H];

    int t = threadIdx.x, w = t >> 5, lane = t & 31;
    int tbase = blockIdx.x * TILE;
    int n0 = g_perm[tbase];
    if (n0 < 0) return;
    int d = g_didx[n0];

    if (t < H) { ssum[t] = 0.f; ssq[t] = 0.f; sb[t] = b[d * H + t]; }
    if (t < FIN) sW[t * 64 + 63] = 0.f;  // pad column (lane 31's z1 slot)

    const float* Wd = W + d * FIN * H;
    for (int idx = t; idx < FIN * H; idx += 256) {
        int i = idx / H, o = idx - i * H;
        sW[i * 64 + o] = Wd[idx];
    }

    // ---- gather (self + neighbor sum) into transposed smem tile
    constexpr int KK = (FIN + 31) / 32;
    for (int r = 0; r < 8; r++) {
        int slot = w * 8 + r;
        int n = g_perm[tbase + slot];
        if (n >= 0) {
            float acc[KK];
#pragma unroll
            for (int k = 0; k < KK; k++) {
                int f = lane + 32 * k;
                acc[k] = (f < FIN) ? in[(size_t)n * FIN + f] : 0.f;
            }
            int s0 = g_off[n], s1 = g_off[n + 1];
            for (int j = s0; j < s1; j++) {
                const float* row = in + (size_t)g_csr[j] * FIN;
#pragma unroll
                for (int k = 0; k < KK; k++) {
                    int f = lane + 32 * k;
                    if (f < FIN) acc[k] += row[f];
                }
            }
            float cnt = (float)(1 + s1 - s0);
#pragma unroll
            for (int k = 0; k < KK; k++) {
                int f = lane + 32 * k;
                if (f < FIN) {
                    float v = acc[k];
                    if (MODE != 0) v = v * g_scale[f] + cnt * g_shift[f];
                    sT[f * SP + slot] = v;
                }
            }
        } else {
#pragma unroll
            for (int k = 0; k < KK; k++) {
                int f = lane + 32 * k;
                if (f < FIN) sT[f * SP + slot] = 0.f;
            }
        }
    }
    __syncthreads();

    // ---- GEMM: warp computes 8 nodes (4 pairs) x 63 outputs via FFMA2
    u64 z0[4], z1[4];
    float bb0 = sb[lane];
    float bb1 = (lane < H - 32) ? sb[32 + lane] : 0.f;
    u64 b0d = pack2(bb0, bb0), b1d = pack2(bb1, bb1);
#pragma unroll
    for (int p = 0; p < 4; p++) { z0[p] = b0d; z1[p] = b1d; }

    int slotbase = w * 8;
    for (int i = 0; i < FIN; i++) {
        float w0 = sW[i * 64 + lane];
        float w1 = sW[i * 64 + 32 + lane];
        u64 w0d = pack2(w0, w0), w1d = pack2(w1, w1);
        const u64* tp = (const u64*)&sT[i * SP + slotbase];
#pragma unroll
        for (int p = 0; p < 4; p++) {
            u64 tv = tp[p];
            z0[p] = fma2(tv, w0d, z0[p]);
            z1[p] = fma2(tv, w1d, z1[p]);
        }
    }

    // ---- epilogue: relu + store + register-aggregated BN stats
    float rs0 = 0.f, rq0 = 0.f, rs1 = 0.f, rq1 = 0.f;
#pragma unroll
    for (int p = 0; p < 4; p++) {
        float a, bv, c2, dv;
        unpack2(z0[p], a, bv);
        unpack2(z1[p], c2, dv);
        int sA = tbase + slotbase + 2 * p;
        int nA = g_perm[sA], nB = g_perm[sA + 1];
        if (nA >= 0) {
            a = fmaxf(a, 0.f); c2 = fmaxf(c2, 0.f);
            zout[nA * H + lane] = a; rs0 += a; rq0 += a * a;
            if (lane < H - 32) { zout[nA * H + 32 + lane] = c2; rs1 += c2; rq1 += c2 * c2; }
        }
        if (nB >= 0) {
            bv = fmaxf(bv, 0.f); dv = fmaxf(dv, 0.f);
            zout[nB * H + lane] = bv; rs0 += bv; rq0 += bv * bv;
            if (lane < H - 32) { zout[nB * H + 32 + lane] = dv; rs1 += dv; rq1 += dv * dv; }
        }
    }
    atomicAdd(&ssum[lane], rs0);
    atomicAdd(&ssq[lane], rq0);
    if (lane < H - 32) {
        atomicAdd(&ssum[32 + lane], rs1);
        atomicAdd(&ssq[32 + lane], rq1);
    }
    __syncthreads();
    if (t < H) {
        atomicAdd(&g_sum[t], ssum[t]);
        atomicAdd(&g_sq[t], ssq[t]);
    }
}

// ---------------- fold BN stats into affine --------------------------------------
__global__ void k_stats(const float* __restrict__ gamma, const float* __restrict__ beta) {
    int t = threadIdx.x;
    if (t >= H) return;
    float mu  = g_sum[t] * (1.f / N_NODES);
    float var = g_sq[t] * (1.f / N_NODES) - mu * mu;
    float sc  = gamma[t] * rsqrtf(var + BN_EPS);
    g_scale[t] = sc;
    g_shift[t] = beta[t] - mu * sc;
    g_sum[t] = 0.f;
    g_sq[t]  = 0.f;
}

// ---------------- node_to_graph linear (FFMA2, 16 nodes/block) -------------------
#define NGN 16
__global__ void __launch_bounds__(128)
k_ng(const float* __restrict__ Wng, const float* __restrict__ bng) {
    __shared__ float shT[H * NGN];  // [feat][node], pitch 16 (pair-aligned)
    int t = threadIdx.x;            // 128 = output index
    int nb = blockIdx.x * NGN;

    for (int k = t; k < NGN * H; k += 128) {
        int nn = k / H, f = k - nn * H;
        shT[f * NGN + nn] = g_zB[(nb + nn) * H + f] * g_scale[f] + g_shift[f];
    }
    __syncthreads();

    float bb = bng[t];
    u64 z[NGN / 2];
    u64 bbd = pack2(bb, bb);
#pragma unroll
    for (int p = 0; p < NGN / 2; p++) z[p] = bbd;

    for (int i = 0; i < H; i++) {
        float wv = Wng[i * PH + t];
        u64 wvd = pack2(wv, wv);
        const u64* tp = (const u64*)&shT[i * NGN];
#pragma unroll
        for (int p = 0; p < NGN / 2; p++) z[p] = fma2(tp[p], wvd, z[p]);
    }
#pragma unroll
    for (int p = 0; p < NGN / 2; p++) {
        float a, b2;
        unpack2(z[p], a, b2);
        g_hn[(size_t)(nb + 2 * p) * PH + t] = a;
        g_hn[(size_t)(nb + 2 * p + 1) * PH + t] = b2;
    }
}

// ---------------- fused readout + tanh + final GEMM (FFMA2) ----------------------
#define GPB 8
__global__ void __launch_bounds__(256)
k_out(const float* __restrict__ Wtr, const float* __restrict__ btr,
      float* __restrict__ out) {
    __shared__ float sgT[2 * PH * GPB];  // [feat][graph], pitch 8 (pair-aligned)
    int t = threadIdx.x;                 // 256 = output index
    int g0 = blockIdx.x * GPB;

    for (int k = t; k < GPB * PH; k += 256) {
        int gl = k >> 7, f = k & 127;
        const float* base = g_hn + (size_t)(g0 + gl) * NPG * PH + f;
        float s = 0.f, m = -3.402823466e38f;
#pragma unroll
        for (int r = 0; r < NPG; r++) {
            float v = base[(size_t)r * PH];
            s += v;
            m = fmaxf(m, v);
        }
        sgT[f * GPB + gl]        = tanhf(s);
        sgT[(PH + f) * GPB + gl] = tanhf(m);
    }
    __syncthreads();

    float bb = btr[t];
    u64 z[GPB / 2];
    u64 bbd = pack2(bb, bb);
#pragma unroll
    for (int p = 0; p < GPB / 2; p++) z[p] = bbd;

    for (int i = 0; i < 2 * PH; i++) {
        float wv = Wtr[i * PD + t];
        u64 wvd = pack2(wv, wv);
        const u64* tp = (const u64*)&sgT[i * GPB];
#pragma unroll
        for (int p = 0; p < GPB / 2; p++) z[p] = fma2(tp[p], wvd, z[p]);
    }
#pragma unroll
    for (int p = 0; p < GPB / 2; p++) {
        float a, b2;
        unpack2(z[p], a, b2);
        out[(size_t)(g0 + 2 * p) * PD + t] = a;
        out[(size_t)(g0 + 2 * p + 1) * PD + t] = b2;
    }
}

// ---------------- launch -----------------------------------------------------------
extern "C" void kernel_launch(void* const* d_in, const int* in_sizes, int n_in,
                              void* d_out, int out_size) {
    const float* feats = (const float*)d_in[0];
    const int*   src   = (const int*)d_in[1];
    const int*   dst   = (const int*)d_in[2];
    const float* W0  = (const float*)d_in[4];
    const float* b0  = (const float*)d_in[5];
    const float* g0  = (const float*)d_in[6];
    const float* be0 = (const float*)d_in[7];
    const float* W1  = (const float*)d_in[8];
    const float* b1  = (const float*)d_in[9];
    const float* g1  = (const float*)d_in[10];
    const float* be1 = (const float*)d_in[11];
    const float* W2  = (const float*)d_in[12];
    const float* b2  = (const float*)d_in[13];
    const float* g2  = (const float*)d_in[14];
    const float* be2 = (const float*)d_in[15];
    const float* Wng = (const float*)d_in[16];
    const float* bng = (const float*)d_in[17];
    const float* Wtr = (const float*)d_in[18];
    const float* btr = (const float*)d_in[19];
    float* out = (float*)d_out;

    // graph build + degree-bucket sort
    k_init<<<(PERM_SZ + 255) / 256, 256>>>();
    k_count<<<(N_EDGES + 255) / 256, 256>>>(dst);
    k_scan1<<<NB1, 256>>>();
    k_scan2<<<1, 256>>>();
    k_scan3<<<(N_NODES + 255) / 256, 256>>>();
    k_boff<<<1, 32>>>();
    k_fill<<<(N_NODES + 255) / 256, 256>>>();
    k_scatter<<<(N_EDGES + 255) / 256, 256>>>(src, dst);

    // 3 NF layers (bucket-batched gather + smem-W GEMM + relu + BN stats)
    k_layer<F0, 0><<<NTILES, 256>>>(feats, W0, b0);
    k_stats<<<1, 64>>>(g0, be0);
    k_layer<H, 1><<<NTILES, 256>>>(nullptr, W1, b1);
    k_stats<<<1, 64>>>(g1, be1);
    k_layer<H, 2><<<NTILES, 256>>>(nullptr, W2, b2);
    k_stats<<<1, 64>>>(g2, be2);

    // node->graph projection, fused readout + tanh + final GEMM
    k_ng<<<N_NODES / NGN, 128>>>(Wng, bng);
    k_out<<<N_GRAPHS / GPB, 256>>>(Wtr, btr, out);
}

// round 3
// speedup vs baseline: 1.7763x; 1.0871x over previous
#include <cuda_runtime.h>
#include <math.h>

#define N_NODES 160000
#define N_EDGES 640000
#define N_GRAPHS 8000
#define NPG 20
#define F0 74
#define H 63
#define MAXD 10
#define PH 128
#define PD 256
#define BN_EPS 1e-5f
#define NB1 157
#define TILE 64
#define NTILES 2510
#define PERM_SZ (NTILES * TILE)
#define ZP 64                    // pitch of intermediate node-feature arrays

// ---------------- device scratch ---------------------------------------------
__device__ int   g_deg[N_NODES];
__device__ int   g_off[N_NODES + 1];
__device__ int   g_cur[N_NODES];
__device__ int   g_csr[N_EDGES];
__device__ int   g_didx[N_NODES];
__device__ int   g_aux[NB1];
__device__ int   g_bcnt[MAXD];
__device__ int   g_bstart[MAXD];
__device__ int   g_bfill[MAXD];
__device__ int   g_perm[PERM_SZ];
__device__ float g_zA[(size_t)N_NODES * ZP];
__device__ float g_zB[(size_t)N_NODES * ZP];
__device__ float g_sg[(size_t)N_GRAPHS * 2 * PH];   // per-graph tanh(sum)|tanh(max)
__device__ float g_sum[64];
__device__ float g_sq[64];
__device__ float g_scale[64];
__device__ float g_shift[64];
__device__ float g_Wp[H * PH];   // affine-folded W_ng
__device__ float g_bp[PH];       // affine-folded b_ng

// ---------------- packed f32x2 helpers ----------------------------------------
typedef unsigned long long u64;
__device__ __forceinline__ u64 fma2(u64 a, u64 b, u64 c) {
    u64 d; asm("fma.rn.f32x2 %0, %1, %2, %3;" : "=l"(d) : "l"(a), "l"(b), "l"(c)); return d;
}
__device__ __forceinline__ u64 add2(u64 a, u64 b) {
    u64 d; asm("add.rn.f32x2 %0, %1, %2;" : "=l"(d) : "l"(a), "l"(b)); return d;
}
__device__ __forceinline__ u64 mul2(u64 a, u64 b) {
    u64 d; asm("mul.rn.f32x2 %0, %1, %2;" : "=l"(d) : "l"(a), "l"(b)); return d;
}
__device__ __forceinline__ u64 pack2(float lo, float hi) {
    u64 d; asm("mov.b64 %0, {%1, %2};" : "=l"(d) : "f"(lo), "f"(hi)); return d;
}
__device__ __forceinline__ void unpack2(u64 v, float& lo, float& hi) {
    asm("mov.b64 {%0, %1}, %2;" : "=f"(lo), "=f"(hi) : "l"(v));
}

// ---------------- init -----------------------------------------------------------
__global__ void k_init() {
    int i = blockIdx.x * blockDim.x + threadIdx.x;
    if (i < PERM_SZ) g_perm[i] = -1;
    if (i < N_NODES) g_deg[i] = 0;
    if (i < 64) { g_sum[i] = 0.f; g_sq[i] = 0.f; }
    if (i < MAXD) g_bcnt[i] = 0;
}

__global__ void k_count(const int* __restrict__ dst) {
    int e = blockIdx.x * blockDim.x + threadIdx.x;
    if (e < N_EDGES) atomicAdd(&g_deg[dst[e]], 1);
}

// ---------------- scan (3 stages) ---------------------------------------------------
__global__ void k_scan1() {
    __shared__ int s[256];
    int t = threadIdx.x;
    int base = blockIdx.x * 1024;
    int v[4]; int mysum = 0;
#pragma unroll
    for (int k = 0; k < 4; k++) {
        int idx = base + t * 4 + k;
        v[k] = (idx < N_NODES) ? g_deg[idx] : 0;
        mysum += v[k];
    }
    s[t] = mysum;
    __syncthreads();
    for (int off = 1; off < 256; off <<= 1) {
        int x = (t >= off) ? s[t - off] : 0;
        __syncthreads();
        s[t] += x;
        __syncthreads();
    }
    int run = s[t] - mysum;
#pragma unroll
    for (int k = 0; k < 4; k++) {
        int idx = base + t * 4 + k;
        if (idx < N_NODES) g_off[idx] = run;
        run += v[k];
    }
    if (t == 255) g_aux[blockIdx.x] = s[255];
}

__global__ void k_scan2() {
    __shared__ int s[256];
    int t = threadIdx.x;
    int v = (t < NB1) ? g_aux[t] : 0;
    s[t] = v;
    __syncthreads();
    for (int off = 1; off < 256; off <<= 1) {
        int x = (t >= off) ? s[t - off] : 0;
        __syncthreads();
        s[t] += x;
        __syncthreads();
    }
    if (t < NB1) g_aux[t] = s[t] - v;
}

__global__ void k_scan3() {
    __shared__ int c[MAXD];
    int t = threadIdx.x;
    if (t < MAXD) c[t] = 0;
    __syncthreads();
    int i = blockIdx.x * blockDim.x + t;
    if (i < N_NODES) {
        int o = g_off[i] + g_aux[i >> 10];
        g_off[i] = o;
        g_cur[i] = o;
        int d = g_deg[i];
        d = (d < 1) ? 1 : (d > MAXD ? MAXD : d);
        g_didx[i] = d - 1;
        atomicAdd(&c[d - 1], 1);
    }
    if (i == 0) g_off[N_NODES] = N_EDGES;
    __syncthreads();
    if (t < MAXD && c[t] > 0) atomicAdd(&g_bcnt[t], c[t]);
}

__global__ void k_boff() {
    if (threadIdx.x == 0) {
        int s = 0;
        for (int d = 0; d < MAXD; d++) {
            g_bstart[d] = s;
            g_bfill[d] = s;
            s += (g_bcnt[d] + TILE - 1) / TILE * TILE;
        }
    }
}

__global__ void k_fill() {
    __shared__ int c[MAXD], base[MAXD];
    int t = threadIdx.x;
    if (t < MAXD) c[t] = 0;
    __syncthreads();
    int i = blockIdx.x * blockDim.x + t;
    int d = 0, r = 0;
    bool valid = (i < N_NODES);
    if (valid) {
        d = g_didx[i];
        r = atomicAdd(&c[d], 1);
    }
    __syncthreads();
    if (t < MAXD && c[t] > 0) base[t] = atomicAdd(&g_bfill[t], c[t]);
    __syncthreads();
    if (valid) g_perm[base[d] + r] = i;
}

__global__ void k_scatter(const int* __restrict__ src, const int* __restrict__ dst) {
    int e = blockIdx.x * blockDim.x + threadIdx.x;
    if (e < N_EDGES) {
        int p = atomicAdd(&g_cur[dst[e]], 1);
        g_csr[p] = src[e];
    }
}

// ---------------- fused NF layer (bucket tiles, smem W, f32x2 everywhere) -------------
// MODE 0: feats (pitch 74, no affine) -> g_zB
// MODE 1: g_zB (affine)               -> g_zA
// MODE 2: g_zA (affine)               -> g_zB
template <int FIN, int MODE>
__global__ void __launch_bounds__(256)
k_layer(const float* __restrict__ ext_in, const float* __restrict__ W,
        const float* __restrict__ b) {
    const float* in   = (MODE == 0) ? ext_in : (MODE == 1 ? g_zB : g_zA);
    float*       zout = (MODE == 1) ? g_zA : g_zB;

    constexpr int SP = 66;
    __shared__ float sW[FIN * 64];
    __shared__ float sT[FIN * SP];
    __shared__ float sb[64];
    __shared__ float ssum[H], ssq[H];

    int t = threadIdx.x, w = t >> 5, lane = t & 31;
    int tbase = blockIdx.x * TILE;
    int n0 = g_perm[tbase];
    if (n0 < 0) return;
    int d = g_didx[n0];

    if (t < H) { ssum[t] = 0.f; ssq[t] = 0.f; sb[t] = b[d * H + t]; }
    if (t < FIN) sW[t * 64 + 63] = 0.f;

    const float* Wd = W + d * FIN * H;
    for (int idx = t; idx < FIN * H; idx += 256) {
        int i = idx / H, o = idx - i * H;
        sW[i * 64 + o] = Wd[idx];
    }

    // ---- gather: packed f32x2 loads + adds
    const u64* in64 = (const u64*)in;
    for (int r = 0; r < 8; r++) {
        int slot = w * 8 + r;
        int n = g_perm[tbase + slot];
        if (n >= 0) {
            if (FIN == F0) {  // MODE 0: 74 floats = 37 u64 per row
                u64 a0 = in64[(size_t)n * 37 + lane];
                u64 a1 = (lane < 5) ? in64[(size_t)n * 37 + 32 + lane] : 0ULL;
                int s0 = g_off[n], s1 = g_off[n + 1];
                for (int j = s0; j < s1; j++) {
                    size_t rb = (size_t)g_csr[j] * 37;
                    a0 = add2(a0, in64[rb + lane]);
                    if (lane < 5) a1 = add2(a1, in64[rb + 32 + lane]);
                }
                float x, y;
                unpack2(a0, x, y);
                sT[(2 * lane) * SP + slot] = x;
                sT[(2 * lane + 1) * SP + slot] = y;
                if (lane < 5) {
                    unpack2(a1, x, y);
                    sT[(64 + 2 * lane) * SP + slot] = x;
                    sT[(65 + 2 * lane) * SP + slot] = y;
                }
            } else {          // MODE 1/2: pitch 64 = 32 u64 per row
                u64 a0 = in64[(size_t)n * 32 + lane];
                int s0 = g_off[n], s1 = g_off[n + 1];
                for (int j = s0; j < s1; j++)
                    a0 = add2(a0, in64[(size_t)g_csr[j] * 32 + lane]);
                float cnt = (float)(1 + s1 - s0);
                u64 sc2 = ((const u64*)g_scale)[lane];
                u64 sh2 = ((const u64*)g_shift)[lane];
                a0 = fma2(a0, sc2, mul2(sh2, pack2(cnt, cnt)));
                float x, y;
                unpack2(a0, x, y);
                sT[(2 * lane) * SP + slot] = x;
                if (lane < 31) sT[(2 * lane + 1) * SP + slot] = y;
            }
        } else {
#pragma unroll
            for (int k = 0; k < (FIN + 31) / 32; k++) {
                int f = lane + 32 * k;
                if (f < FIN) sT[f * SP + slot] = 0.f;
            }
        }
    }
    __syncthreads();

    // ---- GEMM: warp = 8 nodes (4 pairs) x 63 outputs via FFMA2
    u64 z0[4], z1[4];
    float bb0 = sb[lane];
    float bb1 = (lane < H - 32) ? sb[32 + lane] : 0.f;
    u64 b0d = pack2(bb0, bb0), b1d = pack2(bb1, bb1);
#pragma unroll
    for (int p = 0; p < 4; p++) { z0[p] = b0d; z1[p] = b1d; }

    int slotbase = w * 8;
    for (int i = 0; i < FIN; i++) {
        float w0 = sW[i * 64 + lane];
        float w1 = sW[i * 64 + 32 + lane];
        u64 w0d = pack2(w0, w0), w1d = pack2(w1, w1);
        const u64* tp = (const u64*)&sT[i * SP + slotbase];
#pragma unroll
        for (int p = 0; p < 4; p++) {
            u64 tv = tp[p];
            z0[p] = fma2(tv, w0d, z0[p]);
            z1[p] = fma2(tv, w1d, z1[p]);
        }
    }

    // ---- epilogue: relu + pitched store + BN stats
    float rs0 = 0.f, rq0 = 0.f, rs1 = 0.f, rq1 = 0.f;
#pragma unroll
    for (int p = 0; p < 4; p++) {
        float a, bv, c2, dv;
        unpack2(z0[p], a, bv);
        unpack2(z1[p], c2, dv);
        int sA = tbase + slotbase + 2 * p;
        int nA = g_perm[sA], nB = g_perm[sA + 1];
        if (nA >= 0) {
            a = fmaxf(a, 0.f); c2 = fmaxf(c2, 0.f);
            zout[(size_t)nA * ZP + lane] = a; rs0 += a; rq0 += a * a;
            if (lane < H - 32) { zout[(size_t)nA * ZP + 32 + lane] = c2; rs1 += c2; rq1 += c2 * c2; }
        }
        if (nB >= 0) {
            bv = fmaxf(bv, 0.f); dv = fmaxf(dv, 0.f);
            zout[(size_t)nB * ZP + lane] = bv; rs0 += bv; rq0 += bv * bv;
            if (lane < H - 32) { zout[(size_t)nB * ZP + 32 + lane] = dv; rs1 += dv; rq1 += dv * dv; }
        }
    }
    atomicAdd(&ssum[lane], rs0);
    atomicAdd(&ssq[lane], rq0);
    if (lane < H - 32) {
        atomicAdd(&ssum[32 + lane], rs1);
        atomicAdd(&ssq[32 + lane], rq1);
    }
    __syncthreads();
    if (t < H) {
        atomicAdd(&g_sum[t], ssum[t]);
        atomicAdd(&g_sq[t], ssq[t]);
    }
}

// ---------------- BN stats -> affine ------------------------------------------------
__global__ void k_stats(const float* __restrict__ gamma, const float* __restrict__ beta) {
    int t = threadIdx.x;
    if (t < H) {
        float mu  = g_sum[t] * (1.f / N_NODES);
        float var = g_sq[t] * (1.f / N_NODES) - mu * mu;
        float sc  = gamma[t] * rsqrtf(var + BN_EPS);
        g_scale[t] = sc;
        g_shift[t] = beta[t] - mu * sc;
        g_sum[t] = 0.f;
        g_sq[t]  = 0.f;
    } else if (t == 63) {
        g_scale[63] = 0.f;
        g_shift[63] = 0.f;
    }
}

// ---------------- fold last affine into W_ng/b_ng ------------------------------------
__global__ void k_fold(const float* __restrict__ Wng, const float* __restrict__ bng) {
    int t = threadIdx.x;  // 128
    float acc = bng[t];
    for (int i = 0; i < H; i++) {
        float w = Wng[i * PH + t];
        g_Wp[i * PH + t] = g_scale[i] * w;
        acc += g_shift[i] * w;
    }
    g_bp[t] = acc;
}

// ---------------- fused node->graph GEMM + sum/max readout + tanh --------------------
// block: 8 graphs (160 nodes), warp = 1 graph, thread = 4 outputs. dynamic smem.
#define NGF_G 8
__global__ void __launch_bounds__(256)
k_ngf() {
    extern __shared__ float sm[];
    float* sW = sm;                       // 63*128 = 8064
    float* sT = sm + H * PH;              // 63*160 = 10080 (transposed [feat][node])
    float* sStage = sT + H * 160;         // 32*65  = 2080

    int t = threadIdx.x, w = t >> 5, lane = t & 31;
    int nb = blockIdx.x * (NGF_G * NPG);  // 160 nodes per block

    for (int k = t; k < H * PH; k += 256) sW[k] = g_Wp[k];

    // staged transpose: 5 waves of 32 nodes
    const u64* z64 = (const u64*)g_zB;
    for (int wv = 0; wv < 5; wv++) {
#pragma unroll
        for (int r = 0; r < 4; r++) {
            int idx = t + 256 * r;        // < 1024
            int fp = idx & 31, nl = idx >> 5;
            u64 v = z64[(size_t)(nb + wv * 32 + nl) * 32 + fp];
            float x, y;
            unpack2(v, x, y);
            sStage[nl * 65 + 2 * fp] = x;
            sStage[nl * 65 + 2 * fp + 1] = y;
        }
        __syncthreads();
        for (int k = t; k < 32 * H; k += 256) {
            int nl = k & 31, f = k >> 5;  // f: 0..62
            sT[f * 160 + wv * 32 + nl] = sStage[nl * 65 + f];
        }
        __syncthreads();
    }

    // GEMM + reduce: warp owns graph w; 2 chunks x 2 output-halves
    float s[4], m[4];
#pragma unroll
    for (int j = 0; j < 4; j++) { s[j] = 0.f; m[j] = -3.402823466e38f; }

#pragma unroll
    for (int op2 = 0; op2 < 2; op2++) {
#pragma unroll
        for (int c = 0; c < 2; c++) {
            u64 z[5][2];
#pragma unroll
            for (int p = 0; p < 5; p++) { z[p][0] = 0ULL; z[p][1] = 0ULL; }
            for (int i = 0; i < H; i++) {
                const u64* tp = (const u64*)&sT[i * 160 + w * NPG + c * 10];
                float w0 = sW[i * PH + lane + 64 * op2];
                float w1 = sW[i * PH + lane + 32 + 64 * op2];
                u64 w0d = pack2(w0, w0), w1d = pack2(w1, w1);
#pragma unroll
                for (int p = 0; p < 5; p++) {
                    u64 tv = tp[p];
                    z[p][0] = fma2(tv, w0d, z[p][0]);
                    z[p][1] = fma2(tv, w1d, z[p][1]);
                }
            }
#pragma unroll
            for (int p = 0; p < 5; p++) {
#pragma unroll
                for (int q = 0; q < 2; q++) {
                    float a, bv;
                    unpack2(z[p][q], a, bv);
                    int j = op2 * 2 + q;
                    s[j] += a + bv;
                    m[j] = fmaxf(m[j], fmaxf(a, bv));
                }
            }
        }
    }

    int graph = blockIdx.x * NGF_G + w;
#pragma unroll
    for (int j = 0; j < 4; j++) {
        int o = lane + 32 * (j & 1) + 64 * (j >> 1);
        float bo = g_bp[o];
        g_sg[(size_t)graph * 2 * PH + o]      = tanhf(s[j] + (float)NPG * bo);
        g_sg[(size_t)graph * 2 * PH + PH + o] = tanhf(m[j] + bo);
    }
}
#define NGF_SMEM ((H * PH + H * 160 + 32 * 65) * 4)

// ---------------- final GEMM: out = sg @ W_tr + b_tr ---------------------------------
#define GPB 16
__global__ void __launch_bounds__(256)
k_out(const float* __restrict__ Wtr, const float* __restrict__ btr,
      float* __restrict__ out) {
    __shared__ float sgT[2 * PH * 18];   // [feat][graph], pitch 18
    int t = threadIdx.x;
    int g0 = blockIdx.x * GPB;

    for (int k = t; k < GPB * 2 * PH; k += 256) {
        int f = k & 255, gl = k >> 8;
        sgT[f * 18 + gl] = g_sg[(size_t)(g0 + gl) * 2 * PH + f];
    }
    __syncthreads();

    float bb = btr[t];
    u64 z[GPB / 2];
    u64 bbd = pack2(bb, bb);
#pragma unroll
    for (int p = 0; p < GPB / 2; p++) z[p] = bbd;

    for (int i = 0; i < 2 * PH; i++) {
        float wv = Wtr[i * PD + t];
        u64 wvd = pack2(wv, wv);
        const u64* tp = (const u64*)&sgT[i * 18];
#pragma unroll
        for (int p = 0; p < GPB / 2; p++) z[p] = fma2(tp[p], wvd, z[p]);
    }
#pragma unroll
    for (int p = 0; p < GPB / 2; p++) {
        float a, b2;
        unpack2(z[p], a, b2);
        out[(size_t)(g0 + 2 * p) * PD + t] = a;
        out[(size_t)(g0 + 2 * p + 1) * PD + t] = b2;
    }
}

// ---------------- launch ---------------------------------------------------------------
extern "C" void kernel_launch(void* const* d_in, const int* in_sizes, int n_in,
                              void* d_out, int out_size) {
    const float* feats = (const float*)d_in[0];
    const int*   src   = (const int*)d_in[1];
    const int*   dst   = (const int*)d_in[2];
    const float* W0  = (const float*)d_in[4];
    const float* b0  = (const float*)d_in[5];
    const float* g0  = (const float*)d_in[6];
    const float* be0 = (const float*)d_in[7];
    const float* W1  = (const float*)d_in[8];
    const float* b1  = (const float*)d_in[9];
    const float* g1  = (const float*)d_in[10];
    const float* be1 = (const float*)d_in[11];
    const float* W2  = (const float*)d_in[12];
    const float* b2  = (const float*)d_in[13];
    const float* g2  = (const float*)d_in[14];
    const float* be2 = (const float*)d_in[15];
    const float* Wng = (const float*)d_in[16];
    const float* bng = (const float*)d_in[17];
    const float* Wtr = (const float*)d_in[18];
    const float* btr = (const float*)d_in[19];
    float* out = (float*)d_out;

    static bool attr_done = false;
    if (!attr_done) {
        cudaFuncSetAttribute(k_ngf, cudaFuncAttributeMaxDynamicSharedMemorySize, NGF_SMEM);
        attr_done = true;
    }

    // graph build + degree-bucket sort
    k_init<<<(PERM_SZ + 255) / 256, 256>>>();
    k_count<<<(N_EDGES + 255) / 256, 256>>>(dst);
    k_scan1<<<NB1, 256>>>();
    k_scan2<<<1, 256>>>();
    k_scan3<<<(N_NODES + 255) / 256, 256>>>();
    k_boff<<<1, 32>>>();
    k_fill<<<(N_NODES + 255) / 256, 256>>>();
    k_scatter<<<(N_EDGES + 255) / 256, 256>>>(src, dst);

    // 3 NF layers
    k_layer<F0, 0><<<NTILES, 256>>>(feats, W0, b0);
    k_stats<<<1, 64>>>(g0, be0);
    k_layer<H, 1><<<NTILES, 256>>>(nullptr, W1, b1);
    k_stats<<<1, 64>>>(g1, be1);
    k_layer<H, 2><<<NTILES, 256>>>(nullptr, W2, b2);
    k_stats<<<1, 64>>>(g2, be2);

    // fold affine into W_ng, fused node->graph GEMM + readout, final GEMM
    k_fold<<<1, PH>>>(Wng, bng);
    k_ngf<<<N_GRAPHS / NGF_G, 256, NGF_SMEM>>>();
    k_out<<<N_GRAPHS / GPB, 256>>>(Wtr, btr, out);
}